// round 1
// baseline (speedup 1.0000x reference)
#include <cuda_runtime.h>
#include <math.h>

#define BQ   512
#define TQ   1024
#define DQ   4
#define HQ   64
#define G4   256          // 4*H
#define NB   4            // batches per recurrent block
#define NCLS 1098

// ---------------- scratch (static device allocations only) ----------------
__device__ float g_g1[2][(size_t)BQ * TQ * G4];   // layer-1 gate preactivations, per dir (2 x 512MB)
__device__ float g_h0[(size_t)BQ * TQ * 128];     // layer-0 bidir output, concat layout [B][T][128]
__device__ float g_h1last[BQ * 128];              // gathered last timestep of layer 1

__device__ __forceinline__ float sigf(float v) {
    return 1.0f / (1.0f + __expf(-v));
}

// =====================================================================
// Layer 0: bidirectional LSTM, D_IN=4 input term computed in-loop.
// grid = (BQ/NB, 2 dirs), 256 threads. Each block owns NB full sequences.
// Backward direction: input gathered at rev(t), output stored at rev(t),
// which exactly reproduces reverse -> scan -> reverse of the reference.
// =====================================================================
__global__ void __launch_bounds__(256, 2)
lstm_l0_kernel(const float* __restrict__ x, const int* __restrict__ lens,
               const float* __restrict__ WihF, const float* __restrict__ WhhF,
               const float* __restrict__ bihF, const float* __restrict__ bhhF,
               const float* __restrict__ WihB, const float* __restrict__ WhhB,
               const float* __restrict__ bihB, const float* __restrict__ bhhB)
{
    const int dir   = blockIdx.y;
    const int bbase = blockIdx.x * NB;
    const int g     = threadIdx.x;            // gate row 0..255 (i,f,g,o blocks of 64)

    const float* Wih = dir ? WihB : WihF;
    const float* Whh = dir ? WhhB : WhhF;
    const float* bih = dir ? bihB : bihF;
    const float* bhh = dir ? bhhB : bhhF;

    float whh[HQ];
#pragma unroll
    for (int k = 0; k < HQ; ++k) whh[k] = Whh[g * HQ + k];
    float wih[DQ];
#pragma unroll
    for (int k = 0; k < DQ; ++k) wih[k] = Wih[g * DQ + k];
    const float bias = bih[g] + bhh[g];

    __shared__ __align__(16) float hsh[NB][HQ];
    __shared__ float  gpre[NB][G4];
    __shared__ float4 xs[2][NB];
    __shared__ int    lsh[NB];

    const int pb_b = g >> 6, pb_j = g & 63;   // phase-B role: (batch, hidden unit)

    if (g < NB) lsh[g] = lens[bbase + g];
    hsh[pb_b][pb_j] = 0.0f;
    float c = 0.0f;
    __syncthreads();

    // prologue: stage x(t=0) (backward: position len-1)
    if (g < NB) {
        int len = lsh[g];
        int tt  = dir ? (len - 1) : 0;
        xs[0][g] = reinterpret_cast<const float4*>(x)[(size_t)(bbase + g) * TQ + tt];
    }

    for (int t = 0; t < TQ; ++t) {
        // prefetch x(t+1) into registers (hidden behind the step's FMAs)
        float4 xn = make_float4(0.f, 0.f, 0.f, 0.f);
        if (g < NB) {
            int tn  = (t + 1 < TQ) ? (t + 1) : (TQ - 1);
            int len = lsh[g];
            int tt  = tn;
            if (dir) tt = (tn < len) ? (len - 1 - tn) : tn;
            xn = reinterpret_cast<const float4*>(x)[(size_t)(bbase + g) * TQ + tt];
        }
        __syncthreads();   // prev phase-B h writes + staged x visible

        // ---- phase A: gate preactivations, one gate row per thread, NB batches
        float acc[NB];
#pragma unroll
        for (int b = 0; b < NB; ++b) {
            float4 xv = xs[t & 1][b];
            acc[b] = bias + wih[0] * xv.x + wih[1] * xv.y + wih[2] * xv.z + wih[3] * xv.w;
        }
#pragma unroll
        for (int b = 0; b < NB; ++b) {
            const float4* h4 = reinterpret_cast<const float4*>(hsh[b]);
#pragma unroll
            for (int kk = 0; kk < HQ / 4; ++kk) {
                float4 hv = h4[kk];
                acc[b] += whh[4 * kk + 0] * hv.x;
                acc[b] += whh[4 * kk + 1] * hv.y;
                acc[b] += whh[4 * kk + 2] * hv.z;
                acc[b] += whh[4 * kk + 3] * hv.w;
            }
        }
#pragma unroll
        for (int b = 0; b < NB; ++b) gpre[b][g] = acc[b];
        __syncthreads();

        // ---- phase B: pointwise cell update, thread -> (pb_b, pb_j)
        {
            float gi = gpre[pb_b][pb_j];
            float gf = gpre[pb_b][HQ + pb_j];
            float gc = gpre[pb_b][2 * HQ + pb_j];
            float go = gpre[pb_b][3 * HQ + pb_j];
            float si = sigf(gi);
            float sf = sigf(gf);
            float tg = tanhf(gc);
            float so = sigf(go);
            c = sf * c + si * tg;
            float h = so * tanhf(c);
            hsh[pb_b][pb_j] = h;

            int len = lsh[pb_b];
            int ts  = t;
            if (dir) ts = (t < len) ? (len - 1 - t) : t;
            g_h0[((size_t)(bbase + pb_b) * TQ + ts) * 128 + dir * HQ + pb_j] = h;
        }
        if (g < NB) xs[(t + 1) & 1][g] = xn;
    }
}

// =====================================================================
// Layer-1 gate preactivation GEMM: g1[dir][b][s][:] =
//   h0[b, src(s)] (128) . Wih1_dir^T (256) + b_ih + b_hh
// grid = (T/64, B, 2). 64x256 tile, 8x8 microtile, K-chunks of 32.
// =====================================================================
#define GM_ROWS 64
#define GM_KC   32

__global__ void __launch_bounds__(256, 2)
gates1_gemm_kernel(const int* __restrict__ lens,
                   const float* __restrict__ WihF, const float* __restrict__ bihF,
                   const float* __restrict__ bhhF,
                   const float* __restrict__ WihB, const float* __restrict__ bihB,
                   const float* __restrict__ bhhB)
{
    const int dir   = blockIdx.z;
    const int b     = blockIdx.y;
    const int tbase = blockIdx.x * GM_ROWS;
    const int tid   = threadIdx.x;
    const int tx    = tid & 31, ty = tid >> 5;

    const float* Wih = dir ? WihB : WihF;
    const float* bih = dir ? bihB : bihF;
    const float* bhh = dir ? bhhB : bhhF;

    __shared__ __align__(16) float As[GM_ROWS][GM_KC];
    __shared__ float Ws[GM_KC][G4 + 1];        // +1 pad: conflict-free transposed stores

    const int len = lens[b];

    float acc[8][8];
#pragma unroll
    for (int r = 0; r < 8; ++r)
#pragma unroll
        for (int cc = 0; cc < 8; ++cc) acc[r][cc] = 0.0f;

    const float* h0b = g_h0 + (size_t)b * TQ * 128;

    for (int k0 = 0; k0 < 128; k0 += GM_KC) {
        // A tile: 64 rows x 32 K, float4 loads, backward gathers reversed rows
#pragma unroll
        for (int i = 0; i < 2; ++i) {
            int idx = tid + 256 * i;           // 0..511 float4 slots
            int r   = idx >> 3, kq = idx & 7;
            int srow = tbase + r;
            if (dir) srow = (srow < len) ? (len - 1 - srow) : srow;
            float4 v = reinterpret_cast<const float4*>(h0b + (size_t)srow * 128 + k0)[kq];
            reinterpret_cast<float4*>(&As[r][0])[kq] = v;
        }
        // W tile transposed: Ws[k][g] <- Wih[g][k0+k]
#pragma unroll
        for (int m = 0; m < 8; ++m) {
            int gg = (tid >> 3) + 32 * m;
            int kq = tid & 7;
            float4 v = reinterpret_cast<const float4*>(Wih + (size_t)gg * 128 + k0)[kq];
            Ws[4 * kq + 0][gg] = v.x;
            Ws[4 * kq + 1][gg] = v.y;
            Ws[4 * kq + 2][gg] = v.z;
            Ws[4 * kq + 3][gg] = v.w;
        }
        __syncthreads();

#pragma unroll
        for (int k = 0; k < GM_KC; ++k) {
            float a[8], w[8];
#pragma unroll
            for (int r = 0; r < 8; ++r)  a[r]  = As[ty * 8 + r][k];     // broadcast
#pragma unroll
            for (int cc = 0; cc < 8; ++cc) w[cc] = Ws[k][tx + 32 * cc]; // conflict-free
#pragma unroll
            for (int r = 0; r < 8; ++r)
#pragma unroll
                for (int cc = 0; cc < 8; ++cc)
                    acc[r][cc] += a[r] * w[cc];
        }
        __syncthreads();
    }

    float* outp = g_g1[dir] + ((size_t)b * TQ + tbase) * G4;
#pragma unroll
    for (int cc = 0; cc < 8; ++cc) {
        int   col = tx + 32 * cc;
        float bv  = bih[col] + bhh[col];
#pragma unroll
        for (int r = 0; r < 8; ++r) {
            int row = ty * 8 + r;
            outp[(size_t)row * G4 + col] = acc[r][cc] + bv;
        }
    }
}

// =====================================================================
// Layer 1: recurrent loop over precomputed gate preactivations.
// Stores ONLY the final-gather positions:
//   forward:  t == len-1            -> h1last[b][0:64]
//   backward: scan step t == 0 (lands at position len-1) -> h1last[b][64:128]
// =====================================================================
__global__ void __launch_bounds__(256, 2)
lstm_l1_kernel(const int* __restrict__ lens,
               const float* __restrict__ WhhF, const float* __restrict__ WhhB)
{
    const int dir   = blockIdx.y;
    const int bbase = blockIdx.x * NB;
    const int g     = threadIdx.x;

    const float* Whh = dir ? WhhB : WhhF;
    const float* gin = g_g1[dir];

    float whh[HQ];
#pragma unroll
    for (int k = 0; k < HQ; ++k) whh[k] = Whh[g * HQ + k];

    __shared__ __align__(16) float hsh[NB][HQ];
    __shared__ float gpre[NB][G4];
    __shared__ int   lsh[NB];

    const int pb_b = g >> 6, pb_j = g & 63;
    if (g < NB) lsh[g] = lens[bbase + g];
    hsh[pb_b][pb_j] = 0.0f;
    float c = 0.0f;
    __syncthreads();

    // prologue: stage gate preactivations for t=0
    float ldc[NB];
#pragma unroll
    for (int b = 0; b < NB; ++b)
        ldc[b] = gin[((size_t)(bbase + b) * TQ) * G4 + g];

    for (int t = 0; t < TQ; ++t) {
        // prefetch t+1 preactivations (independent of h -> overlaps the FMAs)
        float ldn[NB];
        const int tn = (t + 1 < TQ) ? (t + 1) : (TQ - 1);
#pragma unroll
        for (int b = 0; b < NB; ++b)
            ldn[b] = gin[((size_t)(bbase + b) * TQ + tn) * G4 + g];

        __syncthreads();

        float acc[NB];
#pragma unroll
        for (int b = 0; b < NB; ++b) acc[b] = ldc[b];
#pragma unroll
        for (int b = 0; b < NB; ++b) {
            const float4* h4 = reinterpret_cast<const float4*>(hsh[b]);
#pragma unroll
            for (int kk = 0; kk < HQ / 4; ++kk) {
                float4 hv = h4[kk];
                acc[b] += whh[4 * kk + 0] * hv.x;
                acc[b] += whh[4 * kk + 1] * hv.y;
                acc[b] += whh[4 * kk + 2] * hv.z;
                acc[b] += whh[4 * kk + 3] * hv.w;
            }
        }
#pragma unroll
        for (int b = 0; b < NB; ++b) gpre[b][g] = acc[b];
        __syncthreads();

        {
            float gi = gpre[pb_b][pb_j];
            float gf = gpre[pb_b][HQ + pb_j];
            float gc = gpre[pb_b][2 * HQ + pb_j];
            float go = gpre[pb_b][3 * HQ + pb_j];
            float si = sigf(gi);
            float sf = sigf(gf);
            float tg = tanhf(gc);
            float so = sigf(go);
            c = sf * c + si * tg;
            float h = so * tanhf(c);
            hsh[pb_b][pb_j] = h;

            int  len = lsh[pb_b];
            bool wr  = dir ? (t == 0) : (t == len - 1);
            if (wr)
                g_h1last[(bbase + pb_b) * 128 + dir * HQ + pb_j] = h;
        }
#pragma unroll
        for (int b = 0; b < NB; ++b) ldc[b] = ldn[b];
    }
}

// =====================================================================
// Final head: out[b] = h1last[b] . W_out^T + b_out   (512 x 1098, K=128)
// =====================================================================
__global__ void __launch_bounds__(256)
final_kernel(const float* __restrict__ Wout, const float* __restrict__ bout,
             float* __restrict__ out)
{
    const int b = blockIdx.x;
    __shared__ float hs[128];
    if (threadIdx.x < 128) hs[threadIdx.x] = g_h1last[b * 128 + threadIdx.x];
    __syncthreads();

    for (int cl = threadIdx.x; cl < NCLS; cl += blockDim.x) {
        const float4* w = reinterpret_cast<const float4*>(Wout + (size_t)cl * 128);
        float a = bout[cl];
#pragma unroll
        for (int k = 0; k < 32; ++k) {
            float4 v = w[k];
            a += hs[4 * k + 0] * v.x + hs[4 * k + 1] * v.y
               + hs[4 * k + 2] * v.z + hs[4 * k + 3] * v.w;
        }
        out[b * NCLS + cl] = a;
    }
}

// =====================================================================
extern "C" void kernel_launch(void* const* d_in, const int* in_sizes, int n_in,
                              void* d_out, int out_size)
{
    const float* x     = (const float*)d_in[0];
    const int*   lens  = (const int*)  d_in[1];
    const float* Wih0f = (const float*)d_in[2];
    const float* Whh0f = (const float*)d_in[3];
    const float* bih0f = (const float*)d_in[4];
    const float* bhh0f = (const float*)d_in[5];
    const float* Wih0b = (const float*)d_in[6];
    const float* Whh0b = (const float*)d_in[7];
    const float* bih0b = (const float*)d_in[8];
    const float* bhh0b = (const float*)d_in[9];
    const float* Wih1f = (const float*)d_in[10];
    const float* Whh1f = (const float*)d_in[11];
    const float* bih1f = (const float*)d_in[12];
    const float* bhh1f = (const float*)d_in[13];
    const float* Wih1b = (const float*)d_in[14];
    const float* Whh1b = (const float*)d_in[15];
    const float* bih1b = (const float*)d_in[16];
    const float* bhh1b = (const float*)d_in[17];
    const float* Wout  = (const float*)d_in[18];
    const float* bout  = (const float*)d_in[19];

    dim3 gl(BQ / NB, 2);
    lstm_l0_kernel<<<gl, 256>>>(x, lens,
                                Wih0f, Whh0f, bih0f, bhh0f,
                                Wih0b, Whh0b, bih0b, bhh0b);

    dim3 gg(TQ / GM_ROWS, BQ, 2);
    gates1_gemm_kernel<<<gg, 256>>>(lens, Wih1f, bih1f, bhh1f,
                                    Wih1b, bih1b, bhh1b);

    lstm_l1_kernel<<<gl, 256>>>(lens, Whh1f, Whh1b);

    final_kernel<<<BQ, 256>>>(Wout, bout, (float*)d_out);
}

// round 2
// speedup vs baseline: 1.8697x; 1.8697x over previous
#include <cuda_runtime.h>
#include <math.h>

#define BQ   512
#define TQ   1024
#define DQ   4
#define HQ   64
#define G4   256          // 4*H
#define NB   4            // batches per recurrent block
#define NCLS 1098
#define FB   4            // batches per final-head block

typedef unsigned long long ull;

// ---------------- scratch (static device allocations only) ----------------
__device__ float g_g1[2][(size_t)BQ * TQ * G4];   // layer-1 gate preactivations per dir
__device__ float g_h0[(size_t)BQ * TQ * 128];     // layer-0 bidir output, [B][T][128]
__device__ float g_h1last[BQ * 128];              // gathered last timestep of layer 1

// ---------------- f32x2 packed-math helpers ----------------
__device__ __forceinline__ ull pk2(float lo, float hi) {
    ull r; asm("mov.b64 %0,{%1,%2};" : "=l"(r) : "f"(lo), "f"(hi)); return r;
}
__device__ __forceinline__ void upk2(ull v, float& lo, float& hi) {
    asm("mov.b64 {%0,%1},%2;" : "=f"(lo), "=f"(hi) : "l"(v));
}
__device__ __forceinline__ ull ffma2(ull a, ull b, ull c) {
    ull d; asm("fma.rn.f32x2 %0,%1,%2,%3;" : "=l"(d) : "l"(a), "l"(b), "l"(c)); return d;
}
__device__ __forceinline__ ull fadd2(ull a, ull b) {
    ull d; asm("add.rn.f32x2 %0,%1,%2;" : "=l"(d) : "l"(a), "l"(b)); return d;
}
__device__ __forceinline__ float tanh_fast(float x) {
    float y; asm("tanh.approx.f32 %0,%1;" : "=f"(y) : "f"(x)); return y;
}
__device__ __forceinline__ float sig_fast(float x) {
    return fmaf(0.5f, tanh_fast(0.5f * x), 0.5f);
}

// =====================================================================
// Layer 0: bidirectional LSTM. grid=(BQ/NB, 2), 256 threads.
// Backward dir: input gathered at rev(t), output stored at rev(t).
// =====================================================================
__global__ void __launch_bounds__(256, 2)
lstm_l0_kernel(const float* __restrict__ x, const int* __restrict__ lens,
               const float* __restrict__ WihF, const float* __restrict__ WhhF,
               const float* __restrict__ bihF, const float* __restrict__ bhhF,
               const float* __restrict__ WihB, const float* __restrict__ WhhB,
               const float* __restrict__ bihB, const float* __restrict__ bhhB)
{
    const int dir   = blockIdx.y;
    const int bbase = blockIdx.x * NB;
    const int g     = threadIdx.x;            // gate row 0..255

    const float* Wih = dir ? WihB : WihF;
    const float* Whh = dir ? WhhB : WhhF;
    const float* bih = dir ? bihB : bihF;
    const float* bhh = dir ? bhhB : bhhF;

    ull whh2[HQ / 2];
    {
        const ull* wsrc = reinterpret_cast<const ull*>(Whh + (size_t)g * HQ);
#pragma unroll
        for (int k = 0; k < HQ / 2; ++k) whh2[k] = wsrc[k];
    }
    float wih[DQ];
#pragma unroll
    for (int k = 0; k < DQ; ++k) wih[k] = Wih[g * DQ + k];
    const float bias = bih[g] + bhh[g];

    __shared__ __align__(16) float hsh[NB][HQ];
    __shared__ float  gpre[NB][G4];
    __shared__ float4 xs[2][NB];
    __shared__ int    lsh[NB];

    const int pb_b = g >> 6, pb_j = g & 63;

    if (g < NB) lsh[g] = lens[bbase + g];
    hsh[pb_b][pb_j] = 0.0f;
    float c = 0.0f;
    __syncthreads();

    if (g < NB) {
        int len = lsh[g];
        int tt  = dir ? (len - 1) : 0;
        xs[0][g] = reinterpret_cast<const float4*>(x)[(size_t)(bbase + g) * TQ + tt];
    }

    for (int t = 0; t < TQ; ++t) {
        float4 xn = make_float4(0.f, 0.f, 0.f, 0.f);
        if (g < NB) {
            int tn  = (t + 1 < TQ) ? (t + 1) : (TQ - 1);
            int len = lsh[g];
            int tt  = tn;
            if (dir) tt = (tn < len) ? (len - 1 - tn) : tn;
            xn = reinterpret_cast<const float4*>(x)[(size_t)(bbase + g) * TQ + tt];
        }
        __syncthreads();

        // ---- phase A: gate preactivations (packed f32x2 dot products)
        float acc[NB];
#pragma unroll
        for (int b = 0; b < NB; ++b) {
            float4 xv = xs[t & 1][b];
            float base = bias + wih[0] * xv.x + wih[1] * xv.y
                              + wih[2] * xv.z + wih[3] * xv.w;
            const ull* h2 = reinterpret_cast<const ull*>(hsh[b]);
            ull a0 = 0ull, a1 = 0ull;
#pragma unroll
            for (int kk = 0; kk < HQ / 2; kk += 2) {
                a0 = ffma2(whh2[kk],     h2[kk],     a0);
                a1 = ffma2(whh2[kk + 1], h2[kk + 1], a1);
            }
            float l0, u0, l1, u1;
            upk2(a0, l0, u0); upk2(a1, l1, u1);
            acc[b] = base + ((l0 + u0) + (l1 + u1));
        }
#pragma unroll
        for (int b = 0; b < NB; ++b) gpre[b][g] = acc[b];
        __syncthreads();

        // ---- phase B: pointwise cell update
        {
            float gi = gpre[pb_b][pb_j];
            float gf = gpre[pb_b][HQ + pb_j];
            float gc = gpre[pb_b][2 * HQ + pb_j];
            float go = gpre[pb_b][3 * HQ + pb_j];
            float si = sig_fast(gi);
            float sf = sig_fast(gf);
            float tg = tanh_fast(gc);
            float so = sig_fast(go);
            c = sf * c + si * tg;
            float h = so * tanh_fast(c);
            hsh[pb_b][pb_j] = h;

            int len = lsh[pb_b];
            int ts  = t;
            if (dir) ts = (t < len) ? (len - 1 - t) : t;
            g_h0[((size_t)(bbase + pb_b) * TQ + ts) * 128 + dir * HQ + pb_j] = h;
        }
        if (g < NB) xs[(t + 1) & 1][g] = xn;
    }
}

// =====================================================================
// Layer-1 gate GEMM, packed f32x2. 64x256 tile, 8x8 microtile (as 8x4 pairs).
// A operand staged DUPLICATED in smem so the broadcast side needs no MOV dup.
// =====================================================================
#define GM_ROWS 64
#define GM_KC   32

__global__ void __launch_bounds__(256, 2)
gates1_gemm_kernel(const int* __restrict__ lens,
                   const float* __restrict__ WihF, const float* __restrict__ bihF,
                   const float* __restrict__ bhhF,
                   const float* __restrict__ WihB, const float* __restrict__ bihB,
                   const float* __restrict__ bhhB)
{
    const int dir   = blockIdx.z;
    const int b     = blockIdx.y;
    const int tbase = blockIdx.x * GM_ROWS;
    const int tid   = threadIdx.x;
    const int tx    = tid & 31, ty = tid >> 5;

    const float* Wih = dir ? WihB : WihF;
    const float* bih = dir ? bihB : bihF;
    const float* bhh = dir ? bhhB : bhhF;

    __shared__ ull As2[GM_ROWS][GM_KC + 1];          // each entry = (v, v)
    __shared__ __align__(8) float Ws[GM_KC][G4 + 2]; // transposed W, even pad

    const int len = lens[b];

    ull acc2[8][4];
#pragma unroll
    for (int r = 0; r < 8; ++r)
#pragma unroll
        for (int cc = 0; cc < 4; ++cc) acc2[r][cc] = 0ull;

    const float* h0b = g_h0 + (size_t)b * TQ * 128;

    for (int k0 = 0; k0 < 128; k0 += GM_KC) {
        // A tile: 64 rows x 32 K as duplicated pairs
#pragma unroll
        for (int i = 0; i < 2; ++i) {
            int idx = tid + 256 * i;           // 0..511 float4 slots
            int r   = idx >> 3, kq = idx & 7;
            int srow = tbase + r;
            if (dir) srow = (srow < len) ? (len - 1 - srow) : srow;
            float4 v = reinterpret_cast<const float4*>(h0b + (size_t)srow * 128 + k0)[kq];
            As2[r][4 * kq + 0] = pk2(v.x, v.x);
            As2[r][4 * kq + 1] = pk2(v.y, v.y);
            As2[r][4 * kq + 2] = pk2(v.z, v.z);
            As2[r][4 * kq + 3] = pk2(v.w, v.w);
        }
        // W tile transposed: Ws[k][g] <- Wih[g][k0+k]
#pragma unroll
        for (int m = 0; m < 8; ++m) {
            int gg = (tid >> 3) + 32 * m;
            int kq = tid & 7;
            float4 v = reinterpret_cast<const float4*>(Wih + (size_t)gg * 128 + k0)[kq];
            Ws[4 * kq + 0][gg] = v.x;
            Ws[4 * kq + 1][gg] = v.y;
            Ws[4 * kq + 2][gg] = v.z;
            Ws[4 * kq + 3][gg] = v.w;
        }
        __syncthreads();

#pragma unroll
        for (int k = 0; k < GM_KC; ++k) {
            ull ad[8];
#pragma unroll
            for (int r = 0; r < 8; ++r) ad[r] = As2[ty * 8 + r][k];   // broadcast LDS.64
            ull wv[4];
            const ull* wrow = reinterpret_cast<const ull*>(&Ws[k][0]);
#pragma unroll
            for (int cc = 0; cc < 4; ++cc) wv[cc] = wrow[tx + 32 * cc]; // col pair (2tx+64cc, +1)
#pragma unroll
            for (int r = 0; r < 8; ++r)
#pragma unroll
                for (int cc = 0; cc < 4; ++cc)
                    acc2[r][cc] = ffma2(ad[r], wv[cc], acc2[r][cc]);
        }
        __syncthreads();
    }

    float* outp = g_g1[dir] + ((size_t)b * TQ + tbase) * G4;
#pragma unroll
    for (int cc = 0; cc < 4; ++cc) {
        int  c0  = 2 * tx + 64 * cc;
        ull  bv  = pk2(bih[c0] + bhh[c0], bih[c0 + 1] + bhh[c0 + 1]);
#pragma unroll
        for (int r = 0; r < 8; ++r) {
            int row = ty * 8 + r;
            *reinterpret_cast<ull*>(outp + (size_t)row * G4 + c0) = fadd2(acc2[r][cc], bv);
        }
    }
}

// =====================================================================
// Layer 1: recurrent loop over precomputed gate preactivations.
// =====================================================================
__global__ void __launch_bounds__(256, 2)
lstm_l1_kernel(const int* __restrict__ lens,
               const float* __restrict__ WhhF, const float* __restrict__ WhhB)
{
    const int dir   = blockIdx.y;
    const int bbase = blockIdx.x * NB;
    const int g     = threadIdx.x;

    const float* Whh = dir ? WhhB : WhhF;
    const float* gin = g_g1[dir];

    ull whh2[HQ / 2];
    {
        const ull* wsrc = reinterpret_cast<const ull*>(Whh + (size_t)g * HQ);
#pragma unroll
        for (int k = 0; k < HQ / 2; ++k) whh2[k] = wsrc[k];
    }

    __shared__ __align__(16) float hsh[NB][HQ];
    __shared__ float gpre[NB][G4];
    __shared__ int   lsh[NB];

    const int pb_b = g >> 6, pb_j = g & 63;
    if (g < NB) lsh[g] = lens[bbase + g];
    hsh[pb_b][pb_j] = 0.0f;
    float c = 0.0f;
    __syncthreads();

    float ldc[NB];
#pragma unroll
    for (int b = 0; b < NB; ++b)
        ldc[b] = gin[((size_t)(bbase + b) * TQ) * G4 + g];

    for (int t = 0; t < TQ; ++t) {
        float ldn[NB];
        const int tn = (t + 1 < TQ) ? (t + 1) : (TQ - 1);
#pragma unroll
        for (int b = 0; b < NB; ++b)
            ldn[b] = gin[((size_t)(bbase + b) * TQ + tn) * G4 + g];

        __syncthreads();

        float acc[NB];
#pragma unroll
        for (int b = 0; b < NB; ++b) {
            const ull* h2 = reinterpret_cast<const ull*>(hsh[b]);
            ull a0 = 0ull, a1 = 0ull;
#pragma unroll
            for (int kk = 0; kk < HQ / 2; kk += 2) {
                a0 = ffma2(whh2[kk],     h2[kk],     a0);
                a1 = ffma2(whh2[kk + 1], h2[kk + 1], a1);
            }
            float l0, u0, l1, u1;
            upk2(a0, l0, u0); upk2(a1, l1, u1);
            acc[b] = ldc[b] + ((l0 + u0) + (l1 + u1));
        }
#pragma unroll
        for (int b = 0; b < NB; ++b) gpre[b][g] = acc[b];
        __syncthreads();

        {
            float gi = gpre[pb_b][pb_j];
            float gf = gpre[pb_b][HQ + pb_j];
            float gc = gpre[pb_b][2 * HQ + pb_j];
            float go = gpre[pb_b][3 * HQ + pb_j];
            float si = sig_fast(gi);
            float sf = sig_fast(gf);
            float tg = tanh_fast(gc);
            float so = sig_fast(go);
            c = sf * c + si * tg;
            float h = so * tanh_fast(c);
            hsh[pb_b][pb_j] = h;

            int  len = lsh[pb_b];
            bool wr  = dir ? (t == 0) : (t == len - 1);
            if (wr)
                g_h1last[(bbase + pb_b) * 128 + dir * HQ + pb_j] = h;
        }
#pragma unroll
        for (int b = 0; b < NB; ++b) ldc[b] = ldn[b];
    }
}

// =====================================================================
// Final head: FB batches per block share each W_out row read.
// =====================================================================
__global__ void __launch_bounds__(256)
final_kernel(const float* __restrict__ Wout, const float* __restrict__ bout,
             float* __restrict__ out)
{
    const int bbase = blockIdx.x * FB;
    __shared__ float hs[FB][128];
    for (int i = threadIdx.x; i < FB * 128; i += 256)
        hs[i >> 7][i & 127] = g_h1last[bbase * 128 + i];
    __syncthreads();

    for (int cl = threadIdx.x; cl < NCLS; cl += 256) {
        const float4* w = reinterpret_cast<const float4*>(Wout + (size_t)cl * 128);
        float a[FB];
#pragma unroll
        for (int b = 0; b < FB; ++b) a[b] = bout[cl];
#pragma unroll
        for (int k = 0; k < 32; ++k) {
            float4 v = w[k];
#pragma unroll
            for (int b = 0; b < FB; ++b) {
                a[b] += hs[b][4 * k + 0] * v.x + hs[b][4 * k + 1] * v.y
                      + hs[b][4 * k + 2] * v.z + hs[b][4 * k + 3] * v.w;
            }
        }
#pragma unroll
        for (int b = 0; b < FB; ++b)
            out[(size_t)(bbase + b) * NCLS + cl] = a[b];
    }
}

// =====================================================================
extern "C" void kernel_launch(void* const* d_in, const int* in_sizes, int n_in,
                              void* d_out, int out_size)
{
    const float* x     = (const float*)d_in[0];
    const int*   lens  = (const int*)  d_in[1];
    const float* Wih0f = (const float*)d_in[2];
    const float* Whh0f = (const float*)d_in[3];
    const float* bih0f = (const float*)d_in[4];
    const float* bhh0f = (const float*)d_in[5];
    const float* Wih0b = (const float*)d_in[6];
    const float* Whh0b = (const float*)d_in[7];
    const float* bih0b = (const float*)d_in[8];
    const float* bhh0b = (const float*)d_in[9];
    const float* Wih1f = (const float*)d_in[10];
    const float* Whh1f = (const float*)d_in[11];
    const float* bih1f = (const float*)d_in[12];
    const float* bhh1f = (const float*)d_in[13];
    const float* Wih1b = (const float*)d_in[14];
    const float* Whh1b = (const float*)d_in[15];
    const float* bih1b = (const float*)d_in[16];
    const float* bhh1b = (const float*)d_in[17];
    const float* Wout  = (const float*)d_in[18];
    const float* bout  = (const float*)d_in[19];

    dim3 gl(BQ / NB, 2);
    lstm_l0_kernel<<<gl, 256>>>(x, lens,
                                Wih0f, Whh0f, bih0f, bhh0f,
                                Wih0b, Whh0b, bih0b, bhh0b);

    dim3 gg(TQ / GM_ROWS, BQ, 2);
    gates1_gemm_kernel<<<gg, 256>>>(lens, Wih1f, bih1f, bhh1f,
                                    Wih1b, bih1b, bhh1b);

    lstm_l1_kernel<<<gl, 256>>>(lens, Whh1f, Whh1b);

    final_kernel<<<BQ / FB, 256>>>(Wout, bout, (float*)d_out);
}

// round 3
// speedup vs baseline: 3.1425x; 1.6808x over previous
#include <cuda_runtime.h>
#include <math.h>

#define BQ   512
#define TQ   1024
#define DQ   4
#define HQ   64
#define G4   256          // 4*H
#define NB   4            // batches per recurrent block
#define NCLS 1098
#define FB   4            // batches per final-head block

typedef unsigned long long ull;

// ---------------- scratch (static device allocations only) ----------------
__device__ float g_g1[2][(size_t)BQ * TQ * G4];   // layer-1 gate preactivations per dir
__device__ float g_h0[(size_t)BQ * TQ * 128];     // layer-0 bidir output, [B][T][128]
__device__ float g_h1last[BQ * 128];              // gathered last timestep of layer 1
__device__ float g_WT[2][128 * G4];               // Wih1 transposed: [dir][k][gate]

// ---------------- f32x2 packed-math helpers ----------------
__device__ __forceinline__ ull pk2(float lo, float hi) {
    ull r; asm("mov.b64 %0,{%1,%2};" : "=l"(r) : "f"(lo), "f"(hi)); return r;
}
__device__ __forceinline__ void upk2(ull v, float& lo, float& hi) {
    asm("mov.b64 {%0,%1},%2;" : "=f"(lo), "=f"(hi) : "l"(v));
}
__device__ __forceinline__ ull ffma2(ull a, ull b, ull c) {
    ull d; asm("fma.rn.f32x2 %0,%1,%2,%3;" : "=l"(d) : "l"(a), "l"(b), "l"(c)); return d;
}
__device__ __forceinline__ float tanh_fast(float x) {
    float y; asm("tanh.approx.f32 %0,%1;" : "=f"(y) : "f"(x)); return y;
}
__device__ __forceinline__ float sig_fast(float x) {
    return fmaf(0.5f, tanh_fast(0.5f * x), 0.5f);
}

// block (0..255) -> sorted group id: pairs co-resident blocks (bid, bid+148)
// with (long, short) sequence groups so per-SM step totals are ~balanced.
__device__ __forceinline__ void block_to_group(int bid, int& dir, int& xb) {
    int j = (bid < 148) ? bid : (403 - bid);
    dir = j & 1;
    xb  = j >> 1;
}

// =====================================================================
// Layer 0: bidirectional LSTM, truncated at per-block max length.
// =====================================================================
__global__ void __launch_bounds__(256, 2)
lstm_l0_kernel(const float* __restrict__ x, const int* __restrict__ lens,
               const float* __restrict__ WihF, const float* __restrict__ WhhF,
               const float* __restrict__ bihF, const float* __restrict__ bhhF,
               const float* __restrict__ WihB, const float* __restrict__ WhhB,
               const float* __restrict__ bihB, const float* __restrict__ bhhB)
{
    int dir, xb;
    block_to_group(blockIdx.x, dir, xb);
    const int bbase = xb * NB;
    const int g     = threadIdx.x;            // gate row 0..255

    const float* Wih = dir ? WihB : WihF;
    const float* Whh = dir ? WhhB : WhhF;
    const float* bih = dir ? bihB : bihF;
    const float* bhh = dir ? bhhB : bhhF;

    ull whh2[HQ / 2];
    {
        const ull* wsrc = reinterpret_cast<const ull*>(Whh + (size_t)g * HQ);
#pragma unroll
        for (int k = 0; k < HQ / 2; ++k) whh2[k] = wsrc[k];
    }
    float wih[DQ];
#pragma unroll
    for (int k = 0; k < DQ; ++k) wih[k] = Wih[g * DQ + k];
    const float bias = bih[g] + bhh[g];

    __shared__ __align__(16) float hsh[NB][HQ];
    __shared__ float  gpre[NB][G4];
    __shared__ float4 xs[2][NB];
    __shared__ int    lsh[NB];

    const int pb_b = g >> 6, pb_j = g & 63;

    if (g < NB) lsh[g] = lens[bbase + g];
    hsh[pb_b][pb_j] = 0.0f;
    float c = 0.0f;
    __syncthreads();

    const int maxlen = lsh[0];                // lens sorted descending

    if (g < NB) {
        int len = lsh[g];
        int tt  = dir ? (len - 1) : 0;
        xs[0][g] = reinterpret_cast<const float4*>(x)[(size_t)(bbase + g) * TQ + tt];
    }

    for (int t = 0; t < maxlen; ++t) {
        float4 xn = make_float4(0.f, 0.f, 0.f, 0.f);
        if (g < NB) {
            int tn  = (t + 1 < maxlen) ? (t + 1) : t;
            int len = lsh[g];
            int tt  = tn;
            if (dir) tt = (tn < len) ? (len - 1 - tn) : tn;
            xn = reinterpret_cast<const float4*>(x)[(size_t)(bbase + g) * TQ + tt];
        }
        __syncthreads();

        // ---- phase A: gate preactivations (packed f32x2, LDS.128 h reads)
        float acc[NB];
#pragma unroll
        for (int b = 0; b < NB; ++b) {
            float4 xv = xs[t & 1][b];
            float base = bias + wih[0] * xv.x + wih[1] * xv.y
                              + wih[2] * xv.z + wih[3] * xv.w;
            const ulonglong2* h2 = reinterpret_cast<const ulonglong2*>(hsh[b]);
            ull a0 = 0ull, a1 = 0ull;
#pragma unroll
            for (int kk = 0; kk < HQ / 4; ++kk) {
                ulonglong2 hv = h2[kk];
                a0 = ffma2(whh2[2 * kk],     hv.x, a0);
                a1 = ffma2(whh2[2 * kk + 1], hv.y, a1);
            }
            float l0, u0, l1, u1;
            upk2(a0, l0, u0); upk2(a1, l1, u1);
            acc[b] = base + ((l0 + u0) + (l1 + u1));
        }
#pragma unroll
        for (int b = 0; b < NB; ++b) gpre[b][g] = acc[b];
        __syncthreads();

        // ---- phase B: pointwise cell update
        {
            float gi = gpre[pb_b][pb_j];
            float gf = gpre[pb_b][HQ + pb_j];
            float gc = gpre[pb_b][2 * HQ + pb_j];
            float go = gpre[pb_b][3 * HQ + pb_j];
            float si = sig_fast(gi);
            float sf = sig_fast(gf);
            float tg = tanh_fast(gc);
            float so = sig_fast(go);
            c = sf * c + si * tg;
            float h = so * tanh_fast(c);
            hsh[pb_b][pb_j] = h;

            int len = lsh[pb_b];
            int ts  = t;
            if (dir) ts = (t < len) ? (len - 1 - t) : t;
            g_h0[((size_t)(bbase + pb_b) * TQ + ts) * 128 + dir * HQ + pb_j] = h;
        }
        if (g < NB) xs[(t + 1) & 1][g] = xn;
    }
}

// =====================================================================
// Wih1 transpose pre-kernel: g_WT[dir][k][g] = Wih1_dir[g][k]
// =====================================================================
__global__ void transpose_w_kernel(const float* __restrict__ WihF,
                                   const float* __restrict__ WihB)
{
    const float* W  = blockIdx.x ? WihB : WihF;
    float*       WT = g_WT[blockIdx.x];
    const int g = threadIdx.x;               // 0..255
    const float4* wrow = reinterpret_cast<const float4*>(W + (size_t)g * 128);
#pragma unroll
    for (int k4 = 0; k4 < 32; ++k4) {
        float4 v = wrow[k4];
        WT[(4 * k4 + 0) * G4 + g] = v.x;
        WT[(4 * k4 + 1) * G4 + g] = v.y;
        WT[(4 * k4 + 2) * G4 + g] = v.z;
        WT[(4 * k4 + 3) * G4 + g] = v.w;
    }
}

// =====================================================================
// Layer-1 gate GEMM, packed f32x2, k-major duplicated A tile.
// 64x256 tile, 8x8 microtile (8 rows x 4 col-pairs), GM_KC=16.
// Tiles entirely past the sequence end exit immediately.
// =====================================================================
#define GM_ROWS 64
#define GM_KC   16

__global__ void __launch_bounds__(256, 2)
gates1_gemm_kernel(const int* __restrict__ lens,
                   const float* __restrict__ bihF, const float* __restrict__ bhhF,
                   const float* __restrict__ bihB, const float* __restrict__ bhhB)
{
    const int dir   = blockIdx.z;
    const int b     = blockIdx.y;
    const int tbase = blockIdx.x * GM_ROWS;

    const int len = lens[b];
    if (tbase >= len) return;                 // rows >= len are never consumed

    const int tid = threadIdx.x;
    const int tx  = tid & 31, ty = tid >> 5;

    const float* bih = dir ? bihB : bihF;
    const float* bhh = dir ? bhhB : bhhF;
    const float* WT  = g_WT[dir];

    __shared__ ull   As2T[GM_KC][GM_ROWS + 2];     // [k][row], (v,v) pairs, 16B-aligned rows
    __shared__ float Ws[GM_KC][G4];                // [k][gate]

    ull acc2[8][4];
#pragma unroll
    for (int r = 0; r < 8; ++r)
#pragma unroll
        for (int cc = 0; cc < 4; ++cc) acc2[r][cc] = 0ull;

    const float* h0b = g_h0 + (size_t)b * TQ * 128;

    for (int k0 = 0; k0 < 128; k0 += GM_KC) {
        // A tile: 64 rows x 16 k, one float4 per thread, stored dup'd k-major
        {
            int r  = tid >> 2, kq = tid & 3;
            int srow = tbase + r;
            if (dir) srow = (srow < len) ? (len - 1 - srow) : srow;
            float4 v = *reinterpret_cast<const float4*>(h0b + (size_t)srow * 128 + k0 + 4 * kq);
            As2T[4 * kq + 0][r] = pk2(v.x, v.x);
            As2T[4 * kq + 1][r] = pk2(v.y, v.y);
            As2T[4 * kq + 2][r] = pk2(v.z, v.z);
            As2T[4 * kq + 3][r] = pk2(v.w, v.w);
        }
        // W tile from pre-transposed WT: coalesced float4 in, STS.128 out
#pragma unroll
        for (int i = 0; i < 4; ++i) {
            int idx = tid + 256 * i;               // 0..1023 float4 slots
            int k   = idx >> 6, c4 = idx & 63;
            float4 v = *reinterpret_cast<const float4*>(WT + (size_t)(k0 + k) * G4 + 4 * c4);
            *reinterpret_cast<float4*>(&Ws[k][4 * c4]) = v;
        }
        __syncthreads();

#pragma unroll
        for (int k = 0; k < GM_KC; ++k) {
            const ulonglong2* adp = reinterpret_cast<const ulonglong2*>(&As2T[k][ty * 8]);
            ulonglong2 ad01 = adp[0], ad23 = adp[1], ad45 = adp[2], ad67 = adp[3];
            ull ad[8] = { ad01.x, ad01.y, ad23.x, ad23.y, ad45.x, ad45.y, ad67.x, ad67.y };
            const ulonglong2* wp = reinterpret_cast<const ulonglong2*>(&Ws[k][0]);
            ulonglong2 w01 = wp[tx];               // cols 4tx .. 4tx+3
            ulonglong2 w23 = wp[tx + 32];          // cols 128+4tx .. 128+4tx+3
#pragma unroll
            for (int r = 0; r < 8; ++r) {
                acc2[r][0] = ffma2(ad[r], w01.x, acc2[r][0]);
                acc2[r][1] = ffma2(ad[r], w01.y, acc2[r][1]);
                acc2[r][2] = ffma2(ad[r], w23.x, acc2[r][2]);
                acc2[r][3] = ffma2(ad[r], w23.y, acc2[r][3]);
            }
        }
        __syncthreads();
    }

    // epilogue: bias add + coalesced float4 stores
    const float4* bi4 = reinterpret_cast<const float4*>(bih);
    const float4* bh4 = reinterpret_cast<const float4*>(bhh);
    float4 ba = bi4[tx],      bb = bh4[tx];
    float4 bv1 = make_float4(ba.x + bb.x, ba.y + bb.y, ba.z + bb.z, ba.w + bb.w);
    ba = bi4[tx + 32]; bb = bh4[tx + 32];
    float4 bv2 = make_float4(ba.x + bb.x, ba.y + bb.y, ba.z + bb.z, ba.w + bb.w);

    float* outp = g_g1[dir] + ((size_t)b * TQ + tbase) * G4;
#pragma unroll
    for (int r = 0; r < 8; ++r) {
        int row = ty * 8 + r;
        float l0, u0, l1, u1;
        upk2(acc2[r][0], l0, u0); upk2(acc2[r][1], l1, u1);
        float4 o1 = make_float4(l0 + bv1.x, u0 + bv1.y, l1 + bv1.z, u1 + bv1.w);
        upk2(acc2[r][2], l0, u0); upk2(acc2[r][3], l1, u1);
        float4 o2 = make_float4(l0 + bv2.x, u0 + bv2.y, l1 + bv2.z, u1 + bv2.w);
        *reinterpret_cast<float4*>(outp + (size_t)row * G4 + 4 * tx)       = o1;
        *reinterpret_cast<float4*>(outp + (size_t)row * G4 + 128 + 4 * tx) = o2;
    }
}

// =====================================================================
// Layer 1: recurrent loop over precomputed gate preactivations, truncated.
// =====================================================================
__global__ void __launch_bounds__(256, 2)
lstm_l1_kernel(const int* __restrict__ lens,
               const float* __restrict__ WhhF, const float* __restrict__ WhhB)
{
    int dir, xb;
    block_to_group(blockIdx.x, dir, xb);
    const int bbase = xb * NB;
    const int g     = threadIdx.x;

    const float* Whh = dir ? WhhB : WhhF;
    const float* gin = g_g1[dir];

    ull whh2[HQ / 2];
    {
        const ull* wsrc = reinterpret_cast<const ull*>(Whh + (size_t)g * HQ);
#pragma unroll
        for (int k = 0; k < HQ / 2; ++k) whh2[k] = wsrc[k];
    }

    __shared__ __align__(16) float hsh[NB][HQ];
    __shared__ float gpre[NB][G4];
    __shared__ int   lsh[NB];

    const int pb_b = g >> 6, pb_j = g & 63;
    if (g < NB) lsh[g] = lens[bbase + g];
    hsh[pb_b][pb_j] = 0.0f;
    float c = 0.0f;
    __syncthreads();

    const int maxlen = lsh[0];

    float ldc[NB];
#pragma unroll
    for (int b = 0; b < NB; ++b)
        ldc[b] = gin[((size_t)(bbase + b) * TQ) * G4 + g];

    for (int t = 0; t < maxlen; ++t) {
        float ldn[NB];
        const int tn = (t + 1 < maxlen) ? (t + 1) : t;
#pragma unroll
        for (int b = 0; b < NB; ++b)
            ldn[b] = gin[((size_t)(bbase + b) * TQ + tn) * G4 + g];

        __syncthreads();

        float acc[NB];
#pragma unroll
        for (int b = 0; b < NB; ++b) {
            const ulonglong2* h2 = reinterpret_cast<const ulonglong2*>(hsh[b]);
            ull a0 = 0ull, a1 = 0ull;
#pragma unroll
            for (int kk = 0; kk < HQ / 4; ++kk) {
                ulonglong2 hv = h2[kk];
                a0 = ffma2(whh2[2 * kk],     hv.x, a0);
                a1 = ffma2(whh2[2 * kk + 1], hv.y, a1);
            }
            float l0, u0, l1, u1;
            upk2(a0, l0, u0); upk2(a1, l1, u1);
            acc[b] = ldc[b] + ((l0 + u0) + (l1 + u1));
        }
#pragma unroll
        for (int b = 0; b < NB; ++b) gpre[b][g] = acc[b];
        __syncthreads();

        {
            float gi = gpre[pb_b][pb_j];
            float gf = gpre[pb_b][HQ + pb_j];
            float gc = gpre[pb_b][2 * HQ + pb_j];
            float go = gpre[pb_b][3 * HQ + pb_j];
            float si = sig_fast(gi);
            float sf = sig_fast(gf);
            float tg = tanh_fast(gc);
            float so = sig_fast(go);
            c = sf * c + si * tg;
            float h = so * tanh_fast(c);
            hsh[pb_b][pb_j] = h;

            int  len = lsh[pb_b];
            bool wr  = dir ? (t == 0) : (t == len - 1);
            if (wr)
                g_h1last[(bbase + pb_b) * 128 + dir * HQ + pb_j] = h;
        }
#pragma unroll
        for (int b = 0; b < NB; ++b) ldc[b] = ldn[b];
    }
}

// =====================================================================
// Final head: FB batches per block share each W_out row read.
// =====================================================================
__global__ void __launch_bounds__(256)
final_kernel(const float* __restrict__ Wout, const float* __restrict__ bout,
             float* __restrict__ out)
{
    const int bbase = blockIdx.x * FB;
    __shared__ float hs[FB][128];
    for (int i = threadIdx.x; i < FB * 128; i += 256)
        hs[i >> 7][i & 127] = g_h1last[bbase * 128 + i];
    __syncthreads();

    for (int cl = threadIdx.x; cl < NCLS; cl += 256) {
        const float4* w = reinterpret_cast<const float4*>(Wout + (size_t)cl * 128);
        float a[FB];
#pragma unroll
        for (int b = 0; b < FB; ++b) a[b] = bout[cl];
#pragma unroll
        for (int k = 0; k < 32; ++k) {
            float4 v = w[k];
#pragma unroll
            for (int b = 0; b < FB; ++b) {
                a[b] += hs[b][4 * k + 0] * v.x + hs[b][4 * k + 1] * v.y
                      + hs[b][4 * k + 2] * v.z + hs[b][4 * k + 3] * v.w;
            }
        }
#pragma unroll
        for (int b = 0; b < FB; ++b)
            out[(size_t)(bbase + b) * NCLS + cl] = a[b];
    }
}

// =====================================================================
extern "C" void kernel_launch(void* const* d_in, const int* in_sizes, int n_in,
                              void* d_out, int out_size)
{
    const float* x     = (const float*)d_in[0];
    const int*   lens  = (const int*)  d_in[1];
    const float* Wih0f = (const float*)d_in[2];
    const float* Whh0f = (const float*)d_in[3];
    const float* bih0f = (const float*)d_in[4];
    const float* bhh0f = (const float*)d_in[5];
    const float* Wih0b = (const float*)d_in[6];
    const float* Whh0b = (const float*)d_in[7];
    const float* bih0b = (const float*)d_in[8];
    const float* bhh0b = (const float*)d_in[9];
    const float* Wih1f = (const float*)d_in[10];
    const float* Whh1f = (const float*)d_in[11];
    const float* bih1f = (const float*)d_in[12];
    const float* bhh1f = (const float*)d_in[13];
    const float* Wih1b = (const float*)d_in[14];
    const float* Whh1b = (const float*)d_in[15];
    const float* bih1b = (const float*)d_in[16];
    const float* bhh1b = (const float*)d_in[17];
    const float* Wout  = (const float*)d_in[18];
    const float* bout  = (const float*)d_in[19];

    transpose_w_kernel<<<2, 256>>>(Wih1f, Wih1b);

    lstm_l0_kernel<<<256, 256>>>(x, lens,
                                 Wih0f, Whh0f, bih0f, bhh0f,
                                 Wih0b, Whh0b, bih0b, bhh0b);

    dim3 gg(TQ / GM_ROWS, BQ, 2);
    gates1_gemm_kernel<<<gg, 256>>>(lens, bih1f, bhh1f, bih1b, bhh1b);

    lstm_l1_kernel<<<256, 256>>>(lens, Whh1f, Whh1b);

    final_kernel<<<BQ / FB, 256>>>(Wout, bout, (float*)d_out);
}